// round 2
// baseline (speedup 1.0000x reference)
#include <cuda_runtime.h>
#include <cuda_bf16.h>
#include <mma.h>
#include <math.h>

using namespace nvcuda;

#define DIM      512
#define MAXLEN   2048
#define SHD      128
#define EXPAND   1024
#define PROJ     2176
#define BATCH    8
#define MTOT     (BATCH*MAXLEN)   // 16384
#define HALF_R   1024             // rope half-dim (feature dim = MAXLEN)

// ------------------- scratch (static device allocations) -------------------
__device__ __nv_bfloat16 g_xn [MTOT*DIM];
__device__ __nv_bfloat16 g_W1b[DIM*PROJ];
__device__ __nv_bfloat16 g_W2b[EXPAND*DIM];
__device__ __nv_bfloat16 g_u  [MTOT*EXPAND];
__device__ __nv_bfloat16 g_v  [MTOT*EXPAND];
__device__ __nv_bfloat16 g_q  [MTOT*SHD];
__device__ __nv_bfloat16 g_k  [MTOT*SHD];
__device__ __nv_bfloat16 g_km [(size_t)BATCH*MAXLEN*MAXLEN];
__device__ __nv_bfloat16 g_o  [MTOT*EXPAND];
__device__ float         g_f  [2*MAXLEN-1];

// ------------------------------ small kernels ------------------------------
__global__ void cvtW1_kernel(const float* __restrict__ W1) {
    int i = blockIdx.x*blockDim.x + threadIdx.x;
    if (i < DIM*PROJ) g_W1b[i] = __float2bfloat16(W1[i]);
}
__global__ void cvtW2_kernel(const float* __restrict__ W2) {
    int i = blockIdx.x*blockDim.x + threadIdx.x;
    if (i < EXPAND*DIM) g_W2b[i] = __float2bfloat16(W2[i]);
}

// RMSNorm: one block (128 thr) per row of 512 floats
__global__ void rmsnorm_kernel(const float* __restrict__ x,
                               const float* __restrict__ norm_scale) {
    int row = blockIdx.x;
    const float4* xr = (const float4*)(x + (size_t)row*DIM);
    float4 v = xr[threadIdx.x];
    float ss = v.x*v.x + v.y*v.y + v.z*v.z + v.w*v.w;
    __shared__ float red[128];
    red[threadIdx.x] = ss;
    __syncthreads();
    #pragma unroll
    for (int o = 64; o > 0; o >>= 1) {
        if (threadIdx.x < o) red[threadIdx.x] += red[threadIdx.x+o];
        __syncthreads();
    }
    float scale = rsqrtf(red[0]*(1.f/DIM) + 1e-6f) * norm_scale[0];
    __nv_bfloat162 p0 = __floats2bfloat162_rn(v.x*scale, v.y*scale);
    __nv_bfloat162 p1 = __floats2bfloat162_rn(v.z*scale, v.w*scale);
    size_t base = (size_t)row*DIM + threadIdx.x*4;
    *(__nv_bfloat162*)&g_xn[base]   = p0;
    *(__nv_bfloat162*)&g_xn[base+2] = p1;
}

// Toeplitz-RoPE closed form: T[m,n] = f(n-m),
// f(d) = sum_j (a1 b1 + a2 b2) cos(th_j d) + (a2 b1 - a1 b2) sin(th_j d)
__global__ void toeplitz_kernel(const float* __restrict__ ra,
                                const float* __restrict__ rb) {
    int idx = blockIdx.x;                 // 0..4094
    float d = (float)(idx - (MAXLEN-1));
    float acc = 0.f;
    for (int j = threadIdx.x; j < HALF_R; j += 256) {
        float a1 = ra[j], a2 = ra[j+HALF_R];
        float b1 = rb[j], b2 = rb[j+HALF_R];
        float P = a1*b1 + a2*b2;
        float Q = a2*b1 - a1*b2;
        float inv = powf(10000.f, -(float)j*(1.f/HALF_R));
        float s, c;
        sincosf(inv*d, &s, &c);
        acc += P*c + Q*s;
    }
    __shared__ float red[256];
    red[threadIdx.x] = acc;
    __syncthreads();
    #pragma unroll
    for (int o = 128; o > 0; o >>= 1) {
        if (threadIdx.x < o) red[threadIdx.x] += red[threadIdx.x+o];
        __syncthreads();
    }
    if (threadIdx.x == 0) g_f[idx] = red[0];
}

// --------------------------- WMMA GEMM common bits --------------------------
// BM=BN=128, BK=32, 256 threads = 8 warps in 2x4 (M x N) grid,
// each warp: 64x32 = 4x2 fragments of 16x16.
#define LDAS 40
#define LDBS 136

#define GEMM_FRAG_DECL                                                         \
    wmma::fragment<wmma::accumulator,16,16,16,float> acc[4][2];                \
    _Pragma("unroll")                                                          \
    for (int i = 0; i < 4; i++)                                                \
        _Pragma("unroll")                                                      \
        for (int j = 0; j < 2; j++) wmma::fill_fragment(acc[i][j], 0.f);       \
    int tid  = threadIdx.x;                                                    \
    int warp = tid >> 5, lane = tid & 31;                                      \
    int wm = warp >> 2, wn = warp & 3;                                         \
    int tr = tid >> 2,  tc = (tid & 3)  * 8;                                   \
    int br = tid >> 4,  bc = (tid & 15) * 8;

#define GEMM_MMA_STEP_RM                                                       \
    _Pragma("unroll")                                                          \
    for (int kk = 0; kk < 2; kk++) {                                           \
        wmma::fragment<wmma::matrix_a,16,16,16,__nv_bfloat16,wmma::row_major> af[4]; \
        wmma::fragment<wmma::matrix_b,16,16,16,__nv_bfloat16,wmma::row_major> bf[2]; \
        _Pragma("unroll")                                                      \
        for (int i = 0; i < 4; i++)                                            \
            wmma::load_matrix_sync(af[i], &As[(wm*64+i*16)*LDAS + kk*16], LDAS); \
        _Pragma("unroll")                                                      \
        for (int j = 0; j < 2; j++)                                            \
            wmma::load_matrix_sync(bf[j], &Bs[(kk*16)*LDBS + wn*32 + j*16], LDBS); \
        _Pragma("unroll")                                                      \
        for (int i = 0; i < 4; i++)                                            \
            _Pragma("unroll")                                                  \
            for (int j = 0; j < 2; j++)                                        \
                wmma::mma_sync(acc[i][j], af[i], bf[j], acc[i][j]);            \
    }

// ------------------------------- GEMM1 -------------------------------------
// uv = silu(xn @ W1 + b1); split into u, v, and (q,k) = base*gamma+beta
__global__ __launch_bounds__(256) void gemm1_kernel(const float* __restrict__ b1,
                                                    const float* __restrict__ gamma,
                                                    const float* __restrict__ beta) {
    __shared__ __align__(16) __nv_bfloat16 As[128*LDAS];
    __shared__ __align__(16) __nv_bfloat16 Bs[32*LDBS];
    __shared__ float ep[8][256];
    GEMM_FRAG_DECL
    const int lda = DIM, ldb = PROJ;
    int row0 = blockIdx.y*128, col0 = blockIdx.x*128;
    for (int kt = 0; kt < DIM; kt += 32) {
        const __nv_bfloat16* Ag = g_xn  + (size_t)row0*lda + kt;
        const __nv_bfloat16* Bg = g_W1b + (size_t)kt*ldb + col0;
        #pragma unroll
        for (int r = tr; r < 128; r += 64)
            *(uint4*)&As[r*LDAS+tc] = *(const uint4*)&Ag[(size_t)r*lda+tc];
        #pragma unroll
        for (int r = br; r < 32; r += 16)
            *(uint4*)&Bs[r*LDBS+bc] = *(const uint4*)&Bg[(size_t)r*ldb+bc];
        __syncthreads();
        GEMM_MMA_STEP_RM
        __syncthreads();
    }
    #pragma unroll
    for (int i = 0; i < 4; i++)
        #pragma unroll
        for (int j = 0; j < 2; j++) {
            wmma::store_matrix_sync(ep[warp], acc[i][j], 16, wmma::mem_row_major);
            __syncwarp();
            int bm = row0 + wm*64 + i*16;
            int bn = col0 + wn*32 + j*16;
            #pragma unroll
            for (int e = 0; e < 8; e++) {
                int t = lane*8 + e;
                int m = bm + (t >> 4), n = bn + (t & 15);
                float val = ep[warp][t] + b1[n];
                val = val / (1.f + expf(-val));     // silu
                if (n < EXPAND)
                    g_u[(size_t)m*EXPAND + n] = __float2bfloat16(val);
                else if (n < 2*EXPAND)
                    g_v[(size_t)m*EXPAND + (n-EXPAND)] = __float2bfloat16(val);
                else {
                    int s = n - 2*EXPAND;
                    g_q[(size_t)m*SHD + s] = __float2bfloat16(val*gamma[s]       + beta[s]);
                    g_k[(size_t)m*SHD + s] = __float2bfloat16(val*gamma[SHD+s]   + beta[SHD+s]);
                }
            }
            __syncwarp();
        }
}

// ------------------------------- qk kernel ----------------------------------
// KM[b,m,n] = relu( q_b[m]·k_b[n]/2048 + f(n-m) )^2    (NT gemm, K=128)
__global__ __launch_bounds__(256) void qk_kernel() {
    __shared__ __align__(16) __nv_bfloat16 As[128*LDAS];
    __shared__ __align__(16) __nv_bfloat16 Bs[128*LDAS];
    __shared__ float ep[8][256];
    wmma::fragment<wmma::accumulator,16,16,16,float> acc[4][2];
    #pragma unroll
    for (int i = 0; i < 4; i++)
        #pragma unroll
        for (int j = 0; j < 2; j++) wmma::fill_fragment(acc[i][j], 0.f);
    int tid  = threadIdx.x;
    int warp = tid >> 5, lane = tid & 31;
    int wm = warp >> 2, wn = warp & 3;
    int tr = tid >> 2,  tc = (tid & 3)*8;

    int b = blockIdx.z;
    const __nv_bfloat16* A = g_q + (size_t)b*MAXLEN*SHD;
    const __nv_bfloat16* B = g_k + (size_t)b*MAXLEN*SHD;
    __nv_bfloat16*       C = g_km + (size_t)b*MAXLEN*MAXLEN;
    int row0 = blockIdx.y*128, col0 = blockIdx.x*128;

    for (int kt = 0; kt < SHD; kt += 32) {
        const __nv_bfloat16* Ag = A + (size_t)row0*SHD + kt;
        const __nv_bfloat16* Bg = B + (size_t)col0*SHD + kt;   // [n][k]
        #pragma unroll
        for (int r = tr; r < 128; r += 64) {
            *(uint4*)&As[r*LDAS+tc] = *(const uint4*)&Ag[(size_t)r*SHD+tc];
            *(uint4*)&Bs[r*LDAS+tc] = *(const uint4*)&Bg[(size_t)r*SHD+tc];
        }
        __syncthreads();
        #pragma unroll
        for (int kk = 0; kk < 2; kk++) {
            wmma::fragment<wmma::matrix_a,16,16,16,__nv_bfloat16,wmma::row_major> af[4];
            wmma::fragment<wmma::matrix_b,16,16,16,__nv_bfloat16,wmma::col_major> bf[2];
            #pragma unroll
            for (int i = 0; i < 4; i++)
                wmma::load_matrix_sync(af[i], &As[(wm*64+i*16)*LDAS + kk*16], LDAS);
            #pragma unroll
            for (int j = 0; j < 2; j++)
                wmma::load_matrix_sync(bf[j], &Bs[(wn*32+j*16)*LDAS + kk*16], LDAS);
            #pragma unroll
            for (int i = 0; i < 4; i++)
                #pragma unroll
                for (int j = 0; j < 2; j++)
                    wmma::mma_sync(acc[i][j], af[i], bf[j], acc[i][j]);
        }
        __syncthreads();
    }
    #pragma unroll
    for (int i = 0; i < 4; i++)
        #pragma unroll
        for (int j = 0; j < 2; j++) {
            wmma::store_matrix_sync(ep[warp], acc[i][j], 16, wmma::mem_row_major);
            __syncwarp();
            int bm = row0 + wm*64 + i*16;
            int bn = col0 + wn*32 + j*16;
            #pragma unroll
            for (int e = 0; e < 8; e++) {
                int t = lane*8 + e;
                int m = bm + (t >> 4), n = bn + (t & 15);
                float s = ep[warp][t]*(1.f/MAXLEN) + g_f[n - m + (MAXLEN-1)];
                s = fmaxf(s, 0.f);
                C[(size_t)m*MAXLEN + n] = __float2bfloat16(s*s);
            }
            __syncwarp();
        }
}

// ------------------------------- GEMM D -------------------------------------
// o[b,m,e] = u[b,m,e] * sum_k KM[b,m,k] * v[b,k,e]    (NN, K=2048)
__global__ __launch_bounds__(256) void gemmD_kernel() {
    __shared__ __align__(16) __nv_bfloat16 As[128*LDAS];
    __shared__ __align__(16) __nv_bfloat16 Bs[32*LDBS];
    __shared__ float ep[8][256];
    GEMM_FRAG_DECL
    int b = blockIdx.z;
    const __nv_bfloat16* A = g_km + (size_t)b*MAXLEN*MAXLEN;
    const __nv_bfloat16* B = g_v  + (size_t)b*MAXLEN*EXPAND;
    const __nv_bfloat16* U = g_u  + (size_t)b*MAXLEN*EXPAND;
    __nv_bfloat16*       O = g_o  + (size_t)b*MAXLEN*EXPAND;
    const int lda = MAXLEN, ldb = EXPAND;
    int row0 = blockIdx.y*128, col0 = blockIdx.x*128;
    for (int kt = 0; kt < MAXLEN; kt += 32) {
        const __nv_bfloat16* Ag = A + (size_t)row0*lda + kt;
        const __nv_bfloat16* Bg = B + (size_t)kt*ldb + col0;
        #pragma unroll
        for (int r = tr; r < 128; r += 64)
            *(uint4*)&As[r*LDAS+tc] = *(const uint4*)&Ag[(size_t)r*lda+tc];
        #pragma unroll
        for (int r = br; r < 32; r += 16)
            *(uint4*)&Bs[r*LDBS+bc] = *(const uint4*)&Bg[(size_t)r*ldb+bc];
        __syncthreads();
        GEMM_MMA_STEP_RM
        __syncthreads();
    }
    #pragma unroll
    for (int i = 0; i < 4; i++)
        #pragma unroll
        for (int j = 0; j < 2; j++) {
            wmma::store_matrix_sync(ep[warp], acc[i][j], 16, wmma::mem_row_major);
            __syncwarp();
            int bm = row0 + wm*64 + i*16;
            int bn = col0 + wn*32 + j*16;
            #pragma unroll
            for (int e = 0; e < 8; e++) {
                int t = lane*8 + e;
                int m = bm + (t >> 4), n = bn + (t & 15);
                float uval = __bfloat162float(U[(size_t)m*EXPAND + n]);
                O[(size_t)m*EXPAND + n] = __float2bfloat16(ep[warp][t]*uval);
            }
            __syncwarp();
        }
}

// ------------------------------- GEMM E -------------------------------------
// out = o @ W2 + b2 + x       (NN, M=16384, N=512, K=1024)
__global__ __launch_bounds__(256) void gemmE_kernel(const float* __restrict__ b2,
                                                    const float* __restrict__ x,
                                                    float* __restrict__ out) {
    __shared__ __align__(16) __nv_bfloat16 As[128*LDAS];
    __shared__ __align__(16) __nv_bfloat16 Bs[32*LDBS];
    __shared__ float ep[8][256];
    GEMM_FRAG_DECL
    const int lda = EXPAND, ldb = DIM;
    int row0 = blockIdx.y*128, col0 = blockIdx.x*128;
    for (int kt = 0; kt < EXPAND; kt += 32) {
        const __nv_bfloat16* Ag = g_o   + (size_t)row0*lda + kt;
        const __nv_bfloat16* Bg = g_W2b + (size_t)kt*ldb + col0;
        #pragma unroll
        for (int r = tr; r < 128; r += 64)
            *(uint4*)&As[r*LDAS+tc] = *(const uint4*)&Ag[(size_t)r*lda+tc];
        #pragma unroll
        for (int r = br; r < 32; r += 16)
            *(uint4*)&Bs[r*LDBS+bc] = *(const uint4*)&Bg[(size_t)r*ldb+bc];
        __syncthreads();
        GEMM_MMA_STEP_RM
        __syncthreads();
    }
    #pragma unroll
    for (int i = 0; i < 4; i++)
        #pragma unroll
        for (int j = 0; j < 2; j++) {
            wmma::store_matrix_sync(ep[warp], acc[i][j], 16, wmma::mem_row_major);
            __syncwarp();
            int bm = row0 + wm*64 + i*16;
            int bn = col0 + wn*32 + j*16;
            #pragma unroll
            for (int e = 0; e < 8; e++) {
                int t = lane*8 + e;
                int m = bm + (t >> 4), n = bn + (t & 15);
                out[(size_t)m*DIM + n] = ep[warp][t] + b2[n] + x[(size_t)m*DIM + n];
            }
            __syncwarp();
        }
}

// ------------------------------- launch -------------------------------------
extern "C" void kernel_launch(void* const* d_in, const int* in_sizes, int n_in,
                              void* d_out, int out_size) {
    (void)in_sizes; (void)n_in; (void)out_size;
    const float* x     = (const float*)d_in[0];
    const float* W1    = (const float*)d_in[1];
    const float* b1    = (const float*)d_in[2];
    const float* W2    = (const float*)d_in[3];
    const float* b2    = (const float*)d_in[4];
    const float* ra    = (const float*)d_in[5];
    const float* rb    = (const float*)d_in[6];
    const float* gamma = (const float*)d_in[7];
    const float* beta  = (const float*)d_in[8];
    const float* ns    = (const float*)d_in[9];
    float* out = (float*)d_out;

    cvtW1_kernel<<<(DIM*PROJ + 511)/512, 512>>>(W1);
    cvtW2_kernel<<<(EXPAND*DIM + 511)/512, 512>>>(W2);
    rmsnorm_kernel<<<MTOT, 128>>>(x, ns);
    toeplitz_kernel<<<2*MAXLEN-1, 256>>>(ra, rb);
    gemm1_kernel<<<dim3(PROJ/128, MTOT/128), 256>>>(b1, gamma, beta);
    qk_kernel<<<dim3(MAXLEN/128, MAXLEN/128, BATCH), 256>>>();
    gemmD_kernel<<<dim3(EXPAND/128, MAXLEN/128, BATCH), 256>>>();
    gemmE_kernel<<<dim3(DIM/128, MTOT/128), 256>>>(b2, x, out);
}

// round 4
// speedup vs baseline: 2.3226x; 2.3226x over previous
#include <cuda_runtime.h>
#include <cuda_bf16.h>
#include <cstdint>
#include <math.h>

#define DIM      512
#define MAXLEN   2048
#define SHD      128
#define EXPAND   1024
#define PROJ     2176
#define BATCH    8
#define MTOT     (BATCH*MAXLEN)   // 16384
#define HALF_R   1024

// ------------------- scratch (static device allocations) -------------------
__device__ __nv_bfloat16 g_xn [(size_t)MTOT*DIM];
__device__ __nv_bfloat16 g_W1b[(size_t)DIM*PROJ];
__device__ __nv_bfloat16 g_W2b[(size_t)EXPAND*DIM];
__device__ __nv_bfloat16 g_u  [(size_t)MTOT*EXPAND];
__device__ __nv_bfloat16 g_v  [(size_t)MTOT*EXPAND];
__device__ __nv_bfloat16 g_q  [(size_t)MTOT*SHD];
__device__ __nv_bfloat16 g_k  [(size_t)MTOT*SHD];
__device__ __nv_bfloat16 g_km [(size_t)BATCH*MAXLEN*MAXLEN];
__device__ __nv_bfloat16 g_o  [(size_t)MTOT*EXPAND];
__device__ float         g_f  [2*MAXLEN-1];

// --------------------------- PTX helpers ------------------------------------
__device__ __forceinline__ uint32_t smem_u32(const void* p) {
    uint32_t a;
    asm("{ .reg .u64 t; cvta.to.shared.u64 t, %1; cvt.u32.u64 %0, t; }" : "=r"(a) : "l"(p));
    return a;
}
__device__ __forceinline__ void ldsm4(uint32_t* r, uint32_t a) {
    asm volatile("ldmatrix.sync.aligned.m8n8.x4.shared.b16 {%0,%1,%2,%3}, [%4];"
        : "=r"(r[0]), "=r"(r[1]), "=r"(r[2]), "=r"(r[3]) : "r"(a));
}
__device__ __forceinline__ void ldsm4t(uint32_t* r, uint32_t a) {
    asm volatile("ldmatrix.sync.aligned.m8n8.x4.trans.shared.b16 {%0,%1,%2,%3}, [%4];"
        : "=r"(r[0]), "=r"(r[1]), "=r"(r[2]), "=r"(r[3]) : "r"(a));
}
__device__ __forceinline__ void mma16816(float* c, const uint32_t* a, uint32_t b0, uint32_t b1) {
    asm volatile("mma.sync.aligned.m16n8k16.row.col.f32.bf16.bf16.f32 "
        "{%0,%1,%2,%3}, {%4,%5,%6,%7}, {%8,%9}, {%0,%1,%2,%3};"
        : "+f"(c[0]), "+f"(c[1]), "+f"(c[2]), "+f"(c[3])
        : "r"(a[0]), "r"(a[1]), "r"(a[2]), "r"(a[3]), "r"(b0), "r"(b1));
}
#define CP16(dst, src) \
    asm volatile("cp.async.cg.shared.global [%0], [%1], 16;" :: "r"(dst), "l"(src))
#define CP_COMMIT() asm volatile("cp.async.commit_group;" ::: "memory")
#define CP_WAIT2()  asm volatile("cp.async.wait_group 2;" ::: "memory")

// ----------------------- pipelined mma.sync mainloop ------------------------
// BM=128, BN=128, BK=32, 4 stages, 256 threads = 8 warps (4M x 2N),
// warp tile 32x64 = 2 mtiles x 8 ntiles of m16n8k16.
// smem stage: A 128x(32+8pad) bf16 = 10240B ; B <= 10240B ; stride 20480B.
#define SSTAGE   20480
#define SMEM_DYN (4*SSTAGE)

template<int KTILES, bool BNT>
__device__ __forceinline__ void mainloop(const __nv_bfloat16* A, int lda,
                                         const __nv_bfloat16* B, int ldb,
                                         uint32_t s0, float (&C)[2][8][4]) {
    const int tid  = threadIdx.x;
    const int lane = tid & 31;
    const int warp = tid >> 5;
    const int wm = warp >> 1, wn = warp & 1;

    auto loadA = [&](int kt, int st) {
        const __nv_bfloat16* Ag = A + kt*32;
        uint32_t sa = s0 + st*SSTAGE;
        #pragma unroll
        for (int it = 0; it < 2; it++) {
            int r = (tid >> 2) + it*64, c = (tid & 3)*8;
            CP16(sa + (uint32_t)(r*40 + c)*2, Ag + (size_t)r*lda + c);
        }
    };
    auto loadB = [&](int kt, int st) {
        uint32_t sb = s0 + st*SSTAGE + 10240;
        if constexpr (BNT) {           // B is [N,K] row-major (K-major operand)
            const __nv_bfloat16* Bg = B + kt*32;
            #pragma unroll
            for (int it = 0; it < 2; it++) {
                int r = (tid >> 2) + it*64, c = (tid & 3)*8;
                CP16(sb + (uint32_t)(r*40 + c)*2, Bg + (size_t)r*ldb + c);
            }
        } else {                       // B is [K,N] row-major
            const __nv_bfloat16* Bg = B + (size_t)kt*32*ldb;
            #pragma unroll
            for (int it = 0; it < 2; it++) {
                int r = (tid >> 4) + it*16, c = (tid & 15)*8;
                CP16(sb + (uint32_t)(r*136 + c)*2, Bg + (size_t)r*ldb + c);
            }
        }
    };

    #pragma unroll
    for (int j = 0; j < 3; j++) {
        if (j < KTILES) { loadA(j, j); loadB(j, j); }
        CP_COMMIT();
    }

    for (int kt = 0; kt < KTILES; kt++) {
        int st = kt & 3;
        CP_WAIT2();
        __syncthreads();
        uint32_t sa = s0 + st*SSTAGE, sb = sa + 10240;
        #pragma unroll
        for (int kk = 0; kk < 2; kk++) {
            uint32_t a[2][4];
            #pragma unroll
            for (int mt = 0; mt < 2; mt++) {
                int row = wm*32 + mt*16 + (lane & 15);
                ldsm4(a[mt], sa + (uint32_t)(row*40 + kk*16 + (lane >> 4)*8)*2);
            }
            uint32_t b[4][4];
            #pragma unroll
            for (int nt2 = 0; nt2 < 4; nt2++) {
                if constexpr (BNT) {
                    int nrow = wn*64 + nt2*16 + ((lane >> 4) << 3) + (lane & 7);
                    int kcol = kk*16 + ((lane >> 3) & 1)*8;
                    ldsm4(b[nt2], sb + (uint32_t)(nrow*40 + kcol)*2);
                } else {
                    int krow = kk*16 + (lane & 15);
                    int ncol = wn*64 + nt2*16 + (lane >> 4)*8;
                    ldsm4t(b[nt2], sb + (uint32_t)(krow*136 + ncol)*2);
                }
            }
            #pragma unroll
            for (int mt = 0; mt < 2; mt++)
                #pragma unroll
                for (int nt = 0; nt < 8; nt++)
                    mma16816(C[mt][nt], a[mt], b[nt >> 1][(nt & 1)*2], b[nt >> 1][(nt & 1)*2 + 1]);
        }
        int jn = kt + 3;
        if (jn < KTILES) { loadA(jn, jn & 3); loadB(jn, jn & 3); }
        CP_COMMIT();
    }
}

#define ACC_INIT(C)                                                            \
    float C[2][8][4];                                                          \
    _Pragma("unroll") for (int i = 0; i < 2; i++)                              \
    _Pragma("unroll") for (int j = 0; j < 8; j++)                              \
    _Pragma("unroll") for (int l = 0; l < 4; l++) C[i][j][l] = 0.f;

#define EPI_COORDS                                                             \
    int lane = threadIdx.x & 31, warp = threadIdx.x >> 5;                      \
    int rbase = (blockIdx.y*128) + (warp >> 1)*32 + (lane >> 2);               \
    int cbase = (blockIdx.x*128) + (warp & 1)*64 + (lane & 3)*2;

// ------------------------------ small kernels ------------------------------
__global__ void cvtW1_kernel(const float* __restrict__ W1) {
    int i = blockIdx.x*blockDim.x + threadIdx.x;
    if (i < DIM*PROJ) g_W1b[i] = __float2bfloat16(W1[i]);
}
__global__ void cvtW2_kernel(const float* __restrict__ W2) {
    int i = blockIdx.x*blockDim.x + threadIdx.x;
    if (i < EXPAND*DIM) g_W2b[i] = __float2bfloat16(W2[i]);
}

__global__ void rmsnorm_kernel(const float* __restrict__ x,
                               const float* __restrict__ norm_scale) {
    int row = blockIdx.x;
    const float4* xr = (const float4*)(x + (size_t)row*DIM);
    float4 v = xr[threadIdx.x];
    float ss = v.x*v.x + v.y*v.y + v.z*v.z + v.w*v.w;
    __shared__ float red[128];
    red[threadIdx.x] = ss;
    __syncthreads();
    #pragma unroll
    for (int o = 64; o > 0; o >>= 1) {
        if (threadIdx.x < o) red[threadIdx.x] += red[threadIdx.x+o];
        __syncthreads();
    }
    float scale = rsqrtf(red[0]*(1.f/DIM) + 1e-6f) * norm_scale[0];
    __nv_bfloat162 p0 = __floats2bfloat162_rn(v.x*scale, v.y*scale);
    __nv_bfloat162 p1 = __floats2bfloat162_rn(v.z*scale, v.w*scale);
    size_t base = (size_t)row*DIM + threadIdx.x*4;
    *(__nv_bfloat162*)&g_xn[base]   = p0;
    *(__nv_bfloat162*)&g_xn[base+2] = p1;
}

__global__ void toeplitz_kernel(const float* __restrict__ ra,
                                const float* __restrict__ rb) {
    int idx = blockIdx.x;                 // 0..4094
    float d = (float)(idx - (MAXLEN-1));
    float acc = 0.f;
    for (int j = threadIdx.x; j < HALF_R; j += 256) {
        float a1 = ra[j], a2 = ra[j+HALF_R];
        float b1 = rb[j], b2 = rb[j+HALF_R];
        float P = a1*b1 + a2*b2;
        float Q = a2*b1 - a1*b2;
        float inv = exp2f(-13.287712379549449f * (float)j * (1.f/HALF_R));
        float s, c;
        sincosf(inv*d, &s, &c);
        acc += P*c + Q*s;
    }
    __shared__ float red[256];
    red[threadIdx.x] = acc;
    __syncthreads();
    #pragma unroll
    for (int o = 128; o > 0; o >>= 1) {
        if (threadIdx.x < o) red[threadIdx.x] += red[threadIdx.x+o];
        __syncthreads();
    }
    if (threadIdx.x == 0) g_f[idx] = red[0];
}

// ------------------------------- GEMM1 --------------------------------------
// uv = silu(xn @ W1 + b1); bx<8 -> u, bx<16 -> v, bx==16 -> q/k
__global__ void __launch_bounds__(256,2) mma_gemm1(const float* __restrict__ b1,
                                                   const float* __restrict__ gamma,
                                                   const float* __restrict__ beta) {
    extern __shared__ __align__(16) char smem[];
    uint32_t s0 = smem_u32(smem);
    int row0 = blockIdx.y*128, col0 = blockIdx.x*128;
    ACC_INIT(C)
    mainloop<DIM/32, false>(g_xn + (size_t)row0*DIM, DIM, g_W1b + col0, PROJ, s0, C);
    EPI_COORDS
    #pragma unroll
    for (int mt = 0; mt < 2; mt++)
        #pragma unroll
        for (int nt = 0; nt < 8; nt++) {
            int n = cbase + nt*8;
            float bb0 = __ldg(&b1[n]), bb1 = __ldg(&b1[n+1]);
            #pragma unroll
            for (int h = 0; h < 2; h++) {
                int m = rbase + mt*16 + h*8;
                float v0 = C[mt][nt][h*2]   + bb0;
                float v1 = C[mt][nt][h*2+1] + bb1;
                v0 = v0 / (1.f + __expf(-v0));
                v1 = v1 / (1.f + __expf(-v1));
                if (n < EXPAND) {
                    *(__nv_bfloat162*)&g_u[(size_t)m*EXPAND + n] = __floats2bfloat162_rn(v0, v1);
                } else if (n < 2*EXPAND) {
                    *(__nv_bfloat162*)&g_v[(size_t)m*EXPAND + (n-EXPAND)] = __floats2bfloat162_rn(v0, v1);
                } else {
                    int s = n - 2*EXPAND;
                    float q0 = v0*__ldg(&gamma[s])       + __ldg(&beta[s]);
                    float q1 = v1*__ldg(&gamma[s+1])     + __ldg(&beta[s+1]);
                    float k0 = v0*__ldg(&gamma[SHD+s])   + __ldg(&beta[SHD+s]);
                    float k1 = v1*__ldg(&gamma[SHD+s+1]) + __ldg(&beta[SHD+s+1]);
                    *(__nv_bfloat162*)&g_q[(size_t)m*SHD + s] = __floats2bfloat162_rn(q0, q1);
                    *(__nv_bfloat162*)&g_k[(size_t)m*SHD + s] = __floats2bfloat162_rn(k0, k1);
                }
            }
        }
}

// ------------------------------- qk -----------------------------------------
// KM[b,m,n] = relu(q·k/2048 + f(n-m))^2   (NT, K=128)
__global__ void __launch_bounds__(256,2) mma_qk() {
    extern __shared__ __align__(16) char smem[];
    uint32_t s0 = smem_u32(smem);
    int b = blockIdx.z;
    int row0 = blockIdx.y*128, col0 = blockIdx.x*128;
    ACC_INIT(C)
    mainloop<SHD/32, true>(g_q + (size_t)b*MAXLEN*SHD + (size_t)row0*SHD, SHD,
                           g_k + (size_t)b*MAXLEN*SHD + (size_t)col0*SHD, SHD, s0, C);
    EPI_COORDS
    __nv_bfloat16* KM = g_km + (size_t)b*MAXLEN*MAXLEN;
    #pragma unroll
    for (int mt = 0; mt < 2; mt++)
        #pragma unroll
        for (int h = 0; h < 2; h++) {
            int m = rbase + mt*16 + h*8;
            const float* fp = g_f + (cbase - m + (MAXLEN-1));
            #pragma unroll
            for (int nt = 0; nt < 8; nt++) {
                float s0v = fmaxf(C[mt][nt][h*2]  *(1.f/MAXLEN) + fp[nt*8],   0.f);
                float s1v = fmaxf(C[mt][nt][h*2+1]*(1.f/MAXLEN) + fp[nt*8+1], 0.f);
                *(__nv_bfloat162*)&KM[(size_t)m*MAXLEN + cbase + nt*8] =
                    __floats2bfloat162_rn(s0v*s0v, s1v*s1v);
            }
        }
}

// ------------------------------- GEMM D -------------------------------------
// o = u * (KM @ v)   (NN, K=2048)
__global__ void __launch_bounds__(256,2) mma_gemmD() {
    extern __shared__ __align__(16) char smem[];
    uint32_t s0 = smem_u32(smem);
    int b = blockIdx.z;
    int row0 = blockIdx.y*128, col0 = blockIdx.x*128;
    ACC_INIT(C)
    mainloop<MAXLEN/32, false>(g_km + (size_t)b*MAXLEN*MAXLEN + (size_t)row0*MAXLEN, MAXLEN,
                               g_v  + (size_t)b*MAXLEN*EXPAND + col0, EXPAND, s0, C);
    EPI_COORDS
    #pragma unroll
    for (int mt = 0; mt < 2; mt++)
        #pragma unroll
        for (int h = 0; h < 2; h++) {
            int m = b*MAXLEN + rbase + mt*16 + h*8;
            #pragma unroll
            for (int nt = 0; nt < 8; nt++) {
                size_t gofs = (size_t)m*EXPAND + cbase + nt*8;
                __nv_bfloat162 u2 = *(const __nv_bfloat162*)&g_u[gofs];
                float o0 = C[mt][nt][h*2]   * __bfloat162float(u2.x);
                float o1 = C[mt][nt][h*2+1] * __bfloat162float(u2.y);
                *(__nv_bfloat162*)&g_o[gofs] = __floats2bfloat162_rn(o0, o1);
            }
        }
}

// ------------------------------- GEMM E -------------------------------------
// out = o @ W2 + b2 + x   (NN, K=1024)
__global__ void __launch_bounds__(256,2) mma_gemmE(const float* __restrict__ b2,
                                                   const float* __restrict__ x,
                                                   float* __restrict__ out) {
    extern __shared__ __align__(16) char smem[];
    uint32_t s0 = smem_u32(smem);
    int row0 = blockIdx.y*128, col0 = blockIdx.x*128;
    ACC_INIT(C)
    mainloop<EXPAND/32, false>(g_o + (size_t)row0*EXPAND, EXPAND, g_W2b + col0, DIM, s0, C);
    EPI_COORDS
    #pragma unroll
    for (int mt = 0; mt < 2; mt++)
        #pragma unroll
        for (int nt = 0; nt < 8; nt++) {
            int n = cbase + nt*8;
            float bb0 = __ldg(&b2[n]), bb1 = __ldg(&b2[n+1]);
            #pragma unroll
            for (int h = 0; h < 2; h++) {
                int m = rbase + mt*16 + h*8;
                size_t gofs = (size_t)m*DIM + n;
                float2 xv = *(const float2*)&x[gofs];
                float2 o;
                o.x = C[mt][nt][h*2]   + bb0 + xv.x;
                o.y = C[mt][nt][h*2+1] + bb1 + xv.y;
                *(float2*)&out[gofs] = o;
            }
        }
}

// ------------------------------- launch -------------------------------------
extern "C" void kernel_launch(void* const* d_in, const int* in_sizes, int n_in,
                              void* d_out, int out_size) {
    (void)in_sizes; (void)n_in; (void)out_size;
    const float* x     = (const float*)d_in[0];
    const float* W1    = (const float*)d_in[1];
    const float* b1    = (const float*)d_in[2];
    const float* W2    = (const float*)d_in[3];
    const float* b2    = (const float*)d_in[4];
    const float* ra    = (const float*)d_in[5];
    const float* rb    = (const float*)d_in[6];
    const float* gamma = (const float*)d_in[7];
    const float* beta  = (const float*)d_in[8];
    const float* ns    = (const float*)d_in[9];
    float* out = (float*)d_out;

    static bool attr_done = false;
    if (!attr_done) {
        cudaFuncSetAttribute(mma_gemm1, cudaFuncAttributeMaxDynamicSharedMemorySize, SMEM_DYN);
        cudaFuncSetAttribute(mma_qk,    cudaFuncAttributeMaxDynamicSharedMemorySize, SMEM_DYN);
        cudaFuncSetAttribute(mma_gemmD, cudaFuncAttributeMaxDynamicSharedMemorySize, SMEM_DYN);
        cudaFuncSetAttribute(mma_gemmE, cudaFuncAttributeMaxDynamicSharedMemorySize, SMEM_DYN);
        attr_done = true;
    }

    cvtW1_kernel<<<(DIM*PROJ + 511)/512, 512>>>(W1);
    cvtW2_kernel<<<(EXPAND*DIM + 511)/512, 512>>>(W2);
    rmsnorm_kernel<<<MTOT, 128>>>(x, ns);
    toeplitz_kernel<<<2*MAXLEN-1, 256>>>(ra, rb);

    mma_gemm1<<<dim3(PROJ/128, MTOT/128),            256, SMEM_DYN>>>(b1, gamma, beta);
    mma_qk   <<<dim3(MAXLEN/128, MAXLEN/128, BATCH), 256, SMEM_DYN>>>();
    mma_gemmD<<<dim3(EXPAND/128, MAXLEN/128, BATCH), 256, SMEM_DYN>>>();
    mma_gemmE<<<dim3(DIM/128, MTOT/128),             256, SMEM_DYN>>>(b2, x, out);
}